// round 16
// baseline (speedup 1.0000x reference)
#include <cuda_runtime.h>
#include <cuda_bf16.h>
#include <stdint.h>

#define NB_B     128      // batch rows
#define NB_DIM   1024     // latent dim
#define NB_BINS  16384    // histogram bins / num_outputs
#define NB_MULT  128      // multiplier
#define NB_CROWS 32       // eps rows cached in smem (128KB)

// Bit-exact replica of XLA CPU's vectorized f32 exp (GenerateVF32Exp,
// Cephes polynomial).  DO NOT MODIFY — bit-exactness verified R9.
__device__ __forceinline__ float xla_expf(float input) {
    float x = fminf(fmaxf(input, -88.3762626647949f), 88.3762626647950f);
    float fx = floorf(fmaf(x, 1.44269504088896341f, 0.5f));
    float tmp = __fmul_rn(fx, 0.693359375f);
    float zz  = __fmul_rn(fx, -2.12194440e-4f);
    x = __fsub_rn(x, tmp);
    x = __fsub_rn(x, zz);
    zz = __fmul_rn(x, x);
    float y = fmaf(x, 1.9875691500E-4f, 1.3981999507E-3f);
    y = fmaf(y, x, 8.3334519073E-3f);
    y = fmaf(y, x, 4.1665795894E-2f);
    y = fmaf(y, x, 1.6666665459E-1f);
    y = fmaf(y, x, 5.0000001201E-1f);
    y = fmaf(y, zz, x);
    y = __fadd_rn(1.0f, y);
    int emm0 = ((int)fx + 127) << 23;
    float two_n = __int_as_float(emm0);
    return fmaxf(__fmul_rn(y, two_n), input);
}

// ---------------- Fused kernel: one CTA per batch row ----------------
// Phase A: stream row slice (512KB); per-thread RAW-eps extrema (z extrema
//          derived exactly via monotonicity); first 32 eps rows are stashed
//          in smem (bit-identical floats) for phase B.
// Phase B: first 8 iterations read the smem cache (LDS), remaining 24 re-
//          stream from L2; smem-atomic histogram.
// Tail:    two-pass softmax over integer counts via exp LUT + epilogue.
__global__ __launch_bounds__(1024) void k_fused(const float* __restrict__ zm,
                                                const float* __restrict__ zv,
                                                const float* __restrict__ eps,
                                                const float* __restrict__ x,
                                                float* __restrict__ out) {
    extern __shared__ unsigned smem[];
    unsigned* hist = smem;                          // NB_BINS u32 (64KB)
    float* s_s  = (float*)(smem + NB_BINS);         // NB_DIM
    float* s_zm = s_s + NB_DIM;                     // NB_DIM
    float4* cache4 = (float4*)(s_zm + NB_DIM);      // NB_CROWS*1024 floats (128KB)
    __shared__ float s_rmin[32], s_rmax[32], s_red[32];
    __shared__ float s_bcast[4];
    __shared__ float s_lut[256];                    // expf(-d), d=0..255

    const int b = blockIdx.x;
    const int t = threadIdx.x;
    const int wid = t >> 5, lane = t & 31;

    // ---- prefetch x row (consumed only in epilogue; hides under phase A) ----
    float xv[NB_BINS / 1024];
    {
        const float* xrow = x + (size_t)b * NB_BINS;
        #pragma unroll
        for (int i = 0; i < NB_BINS / 1024; ++i) xv[i] = __ldg(&xrow[t + i * 1024]);
    }

    // zero histogram
    #pragma unroll
    for (int i = 0; i < NB_BINS / 1024; ++i) hist[t + i * 1024] = 0u;

    // exp LUT: expf(-(float)d) — bit-identical to the softmax expf calls
    // (integer args). expf(x)==0 exactly for x <= -104, so d>=256 -> 0.
    if (t < 256) s_lut[t] = expf(-(float)t);

    // Cache z_mean row and stdev row.  0.5*zv is exact (power of 2).
    s_zm[t] = zm[b * NB_DIM + t];
    s_s[t]  = xla_expf(__fmul_rn(0.5f, zv[b * NB_DIM + t]));
    __syncthreads();

    const int jrow = t >> 8;      // 0..3
    const int d4   = t & 255;     // 0..255
    const int d    = d4 * 4;

    const float* __restrict__ row_base = eps + (size_t)b * NB_MULT * NB_DIM;

    // ---------------- Phase A: raw-eps per-column extrema ----------------
    float m0 =  3.402823466e38f, m1 = m0, m2 = m0, m3 = m0;
    float M0 = -3.402823466e38f, M1 = M0, M2 = M0, M3 = M0;

    // First 8 iterations: also stash raw float4s into the smem cache.
    #pragma unroll 4
    for (int it = 0; it < 8; ++it) {
        int j = it * 4 + jrow;
        const float4* ep = reinterpret_cast<const float4*>(row_base + (size_t)j * NB_DIM);
        float4 e = ep[d4];
        cache4[j * 256 + d4] = e;   // conflict-free STS.128
        m0 = fminf(m0, e.x); M0 = fmaxf(M0, e.x);
        m1 = fminf(m1, e.y); M1 = fmaxf(M1, e.y);
        m2 = fminf(m2, e.z); M2 = fmaxf(M2, e.z);
        m3 = fminf(m3, e.w); M3 = fmaxf(M3, e.w);
    }
    #pragma unroll 4
    for (int it = 8; it < 32; ++it) {
        int j = it * 4 + jrow;
        const float4* ep = reinterpret_cast<const float4*>(row_base + (size_t)j * NB_DIM);
        float4 e = ep[d4];
        m0 = fminf(m0, e.x); M0 = fmaxf(M0, e.x);
        m1 = fminf(m1, e.y); M1 = fmaxf(M1, e.y);
        m2 = fminf(m2, e.z); M2 = fmaxf(M2, e.z);
        m3 = fminf(m3, e.w); M3 = fmaxf(M3, e.w);
    }

    const float sm0 = s_zm[d], sm1 = s_zm[d+1], sm2 = s_zm[d+2], sm3 = s_zm[d+3];
    const float ss0 = s_s[d],  ss1 = s_s[d+1],  ss2 = s_s[d+2],  ss3 = s_s[d+3];

    // Transform raw extrema -> z extrema (exact by monotonicity; ss>0).
    // z = zm + s*eps, NON-contracted (plain fmul/fadd). DO NOT fuse.
    float vmin, vmax;
    {
        float l0 = __fadd_rn(sm0, __fmul_rn(ss0, m0));
        float l1 = __fadd_rn(sm1, __fmul_rn(ss1, m1));
        float l2 = __fadd_rn(sm2, __fmul_rn(ss2, m2));
        float l3 = __fadd_rn(sm3, __fmul_rn(ss3, m3));
        float h0 = __fadd_rn(sm0, __fmul_rn(ss0, M0));
        float h1 = __fadd_rn(sm1, __fmul_rn(ss1, M1));
        float h2 = __fadd_rn(sm2, __fmul_rn(ss2, M2));
        float h3 = __fadd_rn(sm3, __fmul_rn(ss3, M3));
        vmin = fminf(fminf(l0, l1), fminf(l2, l3));
        vmax = fmaxf(fmaxf(h0, h1), fmaxf(h2, h3));
    }

    #pragma unroll
    for (int o = 16; o; o >>= 1) {
        vmin = fminf(vmin, __shfl_down_sync(0xffffffffu, vmin, o));
        vmax = fmaxf(vmax, __shfl_down_sync(0xffffffffu, vmax, o));
    }
    if (lane == 0) { s_rmin[wid] = vmin; s_rmax[wid] = vmax; }
    __syncthreads();
    if (wid == 0) {
        vmin = s_rmin[lane];
        vmax = s_rmax[lane];
        #pragma unroll
        for (int o = 16; o; o >>= 1) {
            vmin = fminf(vmin, __shfl_down_sync(0xffffffffu, vmin, o));
            vmax = fmaxf(vmax, __shfl_down_sync(0xffffffffu, vmax, o));
        }
        if (lane == 0) { s_bcast[0] = vmin; s_bcast[1] = vmax; }
    }
    __syncthreads();

    const float mn = s_bcast[0];
    const float dr = __fsub_rn(s_bcast[1], mn);
    // Fast-math reciprocal fold: scaled = (z-mn) * c2, c2 = (1/dr)*16384
    // (*2^14 exact; rnd(16384/dr) == rnd(1/dr)*2^14 bitwise). DO NOT change.
    const float c2 = __fmul_rn(__fdiv_rn(1.0f, dr), 16384.0f);

    // ---------------- Phase B: histogram ----------------
    // First 8 iterations from the smem cache (bit-identical floats), rest
    // from global (L2-hot).
    #pragma unroll 4
    for (int it = 0; it < 8; ++it) {
        int j = it * 4 + jrow;
        float4 e = cache4[j * 256 + d4];            // LDS.128
        float z0 = __fadd_rn(sm0, __fmul_rn(ss0, e.x));
        float z1 = __fadd_rn(sm1, __fmul_rn(ss1, e.y));
        float z2 = __fadd_rn(sm2, __fmul_rn(ss2, e.z));
        float z3 = __fadd_rn(sm3, __fmul_rn(ss3, e.w));
        float c0 = __fmul_rn(__fsub_rn(z0, mn), c2);
        float c1 = __fmul_rn(__fsub_rn(z1, mn), c2);
        float cc = __fmul_rn(__fsub_rn(z2, mn), c2);
        float c3 = __fmul_rn(__fsub_rn(z3, mn), c2);
        int i0 = min(max((int)c0, 0), NB_BINS - 1);
        int i1 = min(max((int)c1, 0), NB_BINS - 1);
        int i2 = min(max((int)cc, 0), NB_BINS - 1);
        int i3 = min(max((int)c3, 0), NB_BINS - 1);
        atomicAdd(&hist[i0], 1u);
        atomicAdd(&hist[i1], 1u);
        atomicAdd(&hist[i2], 1u);
        atomicAdd(&hist[i3], 1u);
    }
    #pragma unroll 8
    for (int it = 8; it < 32; ++it) {
        int j = it * 4 + jrow;
        const float4* ep = reinterpret_cast<const float4*>(row_base + (size_t)j * NB_DIM);
        float4 e = ep[d4];
        float z0 = __fadd_rn(sm0, __fmul_rn(ss0, e.x));
        float z1 = __fadd_rn(sm1, __fmul_rn(ss1, e.y));
        float z2 = __fadd_rn(sm2, __fmul_rn(ss2, e.z));
        float z3 = __fadd_rn(sm3, __fmul_rn(ss3, e.w));
        float c0 = __fmul_rn(__fsub_rn(z0, mn), c2);
        float c1 = __fmul_rn(__fsub_rn(z1, mn), c2);
        float cc = __fmul_rn(__fsub_rn(z2, mn), c2);
        float c3 = __fmul_rn(__fsub_rn(z3, mn), c2);
        int i0 = min(max((int)c0, 0), NB_BINS - 1);
        int i1 = min(max((int)c1, 0), NB_BINS - 1);
        int i2 = min(max((int)cc, 0), NB_BINS - 1);
        int i3 = min(max((int)c3, 0), NB_BINS - 1);
        atomicAdd(&hist[i0], 1u);
        atomicAdd(&hist[i1], 1u);
        atomicAdd(&hist[i2], 1u);
        atomicAdd(&hist[i3], 1u);
    }
    __syncthreads();

    // ---------------- softmax over counts (two-pass, LUT) ----------------
    unsigned cm = 0u;
    #pragma unroll
    for (int i = 0; i < NB_BINS / 1024; ++i) cm = max(cm, hist[t + i * 1024]);
    #pragma unroll
    for (int o = 16; o; o >>= 1) cm = max(cm, __shfl_down_sync(0xffffffffu, cm, o));
    if (lane == 0) s_red[wid] = (float)cm;
    __syncthreads();
    if (wid == 0) {
        float v = s_red[lane];
        #pragma unroll
        for (int o = 16; o; o >>= 1) v = fmaxf(v, __shfl_down_sync(0xffffffffu, v, o));
        if (lane == 0) s_bcast[2] = v;
    }
    __syncthreads();
    const int cmaxi = (int)s_bcast[2];

    // sum of exp(count - cmax) via LUT (bit-identical to expf on int args)
    float sum = 0.0f;
    #pragma unroll
    for (int i = 0; i < NB_BINS / 1024; ++i) {
        int dd = cmaxi - (int)hist[t + i * 1024];
        sum += (dd < 256) ? s_lut[dd] : 0.0f;
    }
    #pragma unroll
    for (int o = 16; o; o >>= 1) sum += __shfl_down_sync(0xffffffffu, sum, o);
    if (lane == 0) s_red[wid] = sum;
    __syncthreads();
    if (wid == 0) {
        float v = s_red[lane];
        #pragma unroll
        for (int o = 16; o; o >>= 1) v += __shfl_down_sync(0xffffffffu, v, o);
        if (lane == 0) s_bcast[3] = v;
    }
    __syncthreads();
    const float rtot = __fdiv_rn(1.0f, s_bcast[3]);

    // epilogue: probs = exp(c-cmax)/total; prune < 1e-10; out = (x*p)*128
    float* orow = out + (size_t)b * NB_BINS;
    #pragma unroll
    for (int i = 0; i < NB_BINS / 1024; ++i) {
        int n = t + i * 1024;
        int dd = cmaxi - (int)hist[n];
        float ev = (dd < 256) ? s_lut[dd] : 0.0f;
        float p = __fmul_rn(ev, rtot);
        if (p < 1e-10f) p = 0.0f;
        orow[n] = __fmul_rn(__fmul_rn(xv[i], p), 128.0f);
    }
}

extern "C" void kernel_launch(void* const* d_in, const int* in_sizes, int n_in,
                              void* d_out, int out_size) {
    const float* zm  = (const float*)d_in[0];
    const float* zv  = (const float*)d_in[1];
    const float* x   = (const float*)d_in[2];
    const float* eps = (const float*)d_in[3];
    float* out = (float*)d_out;

    // hist 64KB + zm/s rows 8KB + eps cache 128KB = 204800 B dynamic smem
    const int smem = NB_BINS * 4 + 2 * NB_DIM * 4 + NB_CROWS * NB_DIM * 4;
    cudaFuncSetAttribute(k_fused, cudaFuncAttributeMaxDynamicSharedMemorySize, smem);

    k_fused<<<NB_B, 1024, smem>>>(zm, zv, eps, x, out);
}